// round 16
// baseline (speedup 1.0000x reference)
#include <cuda_runtime.h>
#include <cuda_fp16.h>
#include <math.h>

#define BATCH 16
#define CH    3
#define H     512
#define W     512
#define HW    (H * W)
#define KRAD  5
#define EPS_PSNR 1e-8f

#define NSEG  64
#define SEG   (H / NSEG)                    // 8 owned rows per pass-2 block
#define XSPL  2
#define P2_BLOCKS (BATCH * NSEG * XSPL)     // 2048

// Packed fp16 intermediates: g_ab[pixel] = half2(xx, yy); g_xy[pixel] = xy
__device__ unsigned int g_ab[BATCH * HW];   // 16.8 MB
__device__ __half       g_xy[BATCH * HW];   //  8.4 MB
__device__ float g_mse[BATCH];      // zero at module load; finalize re-zeros
__device__ float g_cos_sum;
__device__ unsigned int g_count;

// ---------------------------------------------------------------------------
// Pass 1: one image row per block. Products + MSE + horizontal 11-tap.
// grid = BATCH*H = 8192, block = 128 (each thread 4 columns via float4)
// ---------------------------------------------------------------------------
__global__ void __launch_bounds__(128) k_pass1(const float* __restrict__ pred,
                                               const float* __restrict__ tgt) {
    int row = blockIdx.x;
    int b = row >> 9;
    int y = row & (H - 1);
    int tid = threadIdx.x;
    int x4 = tid << 2;

    const float* pr = pred + (size_t)b * CH * HW + (size_t)y * W;
    const float* tr = tgt  + (size_t)b * CH * HW + (size_t)y * W;

    float4 P0 = __ldcs((const float4*)(pr + x4));
    float4 P1 = __ldcs((const float4*)(pr + HW + x4));
    float4 P2 = __ldcs((const float4*)(pr + 2 * HW + x4));
    float4 T0 = __ldcs((const float4*)(tr + x4));
    float4 T1 = __ldcs((const float4*)(tr + HW + x4));
    float4 T2 = __ldcs((const float4*)(tr + 2 * HW + x4));

    float xx0 = P0.x*P0.x + P1.x*P1.x + P2.x*P2.x;
    float xx1 = P0.y*P0.y + P1.y*P1.y + P2.y*P2.y;
    float xx2 = P0.z*P0.z + P1.z*P1.z + P2.z*P2.z;
    float xx3 = P0.w*P0.w + P1.w*P1.w + P2.w*P2.w;

    float yy0 = T0.x*T0.x + T1.x*T1.x + T2.x*T2.x;
    float yy1 = T0.y*T0.y + T1.y*T1.y + T2.y*T2.y;
    float yy2 = T0.z*T0.z + T1.z*T1.z + T2.z*T2.z;
    float yy3 = T0.w*T0.w + T1.w*T1.w + T2.w*T2.w;

    float xy0 = P0.x*T0.x + P1.x*T1.x + P2.x*T2.x;
    float xy1 = P0.y*T0.y + P1.y*T1.y + P2.y*T2.y;
    float xy2 = P0.z*T0.z + P1.z*T1.z + P2.z*T2.z;
    float xy3 = P0.w*T0.w + P1.w*T1.w + P2.w*T2.w;

    float d, msev = 0.f;
    d = P0.x - T0.x; msev += d * d;  d = P0.y - T0.y; msev += d * d;
    d = P0.z - T0.z; msev += d * d;  d = P0.w - T0.w; msev += d * d;
    d = P1.x - T1.x; msev += d * d;  d = P1.y - T1.y; msev += d * d;
    d = P1.z - T1.z; msev += d * d;  d = P1.w - T1.w; msev += d * d;
    d = P2.x - T2.x; msev += d * d;  d = P2.y - T2.y; msev += d * d;
    d = P2.z - T2.z; msev += d * d;  d = P2.w - T2.w; msev += d * d;

    __shared__ float sbuf[3][8 + W + 12];
    __shared__ float sred[4];

    float* a0 = &sbuf[0][8];
    float* a1 = &sbuf[1][8];
    float* a2 = &sbuf[2][8];

    if (tid < 8) { sbuf[0][tid] = 0.f; sbuf[1][tid] = 0.f; sbuf[2][tid] = 0.f; }
    if (tid < 12) {
        sbuf[0][8 + W + tid] = 0.f;
        sbuf[1][8 + W + tid] = 0.f;
        sbuf[2][8 + W + tid] = 0.f;
    }
    *(float4*)(a0 + x4) = make_float4(xx0, xx1, xx2, xx3);
    *(float4*)(a1 + x4) = make_float4(yy0, yy1, yy2, yy3);
    *(float4*)(a2 + x4) = make_float4(xy0, xy1, xy2, xy3);
    __syncthreads();

    size_t o = (size_t)b * HW + (size_t)y * W + x4;

    // horizontal 11-tap windows into dst_[0..3]
#define HWIN(a, dst_)                                                        \
    {                                                                        \
        float4 q0 = *(const float4*)((a) + x4 - 8);                          \
        float4 q1 = *(const float4*)((a) + x4 - 4);                          \
        float4 q2 = *(const float4*)((a) + x4);                              \
        float4 q3 = *(const float4*)((a) + x4 + 4);                          \
        float4 q4 = *(const float4*)((a) + x4 + 8);                          \
        dst_[0] = q0.w + q1.x + q1.y + q1.z + q1.w                           \
                + q2.x + q2.y + q2.z + q2.w + q3.x + q3.y;                   \
        dst_[1] = dst_[0] + q3.z - q0.w;                                     \
        dst_[2] = dst_[1] + q3.w - q1.x;                                     \
        dst_[3] = dst_[2] + q4.x - q1.y;                                     \
    }

    float hxx[4], hyy[4], hxy[4];
    HWIN(a0, hxx)
    HWIN(a1, hyy)
    HWIN(a2, hxy)
#undef HWIN

    // pack: g_ab[o+i] = half2(xx_i, yy_i); g_xy[o+i] = half(xy_i)
    __half2 ab0 = __floats2half2_rn(hxx[0], hyy[0]);
    __half2 ab1 = __floats2half2_rn(hxx[1], hyy[1]);
    __half2 ab2 = __floats2half2_rn(hxx[2], hyy[2]);
    __half2 ab3 = __floats2half2_rn(hxx[3], hyy[3]);
    uint4 pa;
    pa.x = *(const unsigned int*)&ab0;
    pa.y = *(const unsigned int*)&ab1;
    pa.z = *(const unsigned int*)&ab2;
    pa.w = *(const unsigned int*)&ab3;
    *(uint4*)(g_ab + o) = pa;

    __half2 xy01 = __floats2half2_rn(hxy[0], hxy[1]);
    __half2 xy23 = __floats2half2_rn(hxy[2], hxy[3]);
    uint2 pb;
    pb.x = *(const unsigned int*)&xy01;
    pb.y = *(const unsigned int*)&xy23;
    *(uint2*)(g_xy + o) = pb;

    int lane = tid & 31, wid = tid >> 5;
#pragma unroll
    for (int s = 16; s > 0; s >>= 1)
        msev += __shfl_xor_sync(0xffffffffu, msev, s);
    if (lane == 0) sred[wid] = msev;
    __syncthreads();
    if (tid == 0)
        atomicAdd(&g_mse[b], sred[0] + sred[1] + sred[2] + sred[3]);
}

// ---------------------------------------------------------------------------
// Pass 2: vertical 11-tap running sum, register ring for the subtract
// stream, 1 PIXEL PER THREAD to keep ring register cost low.
// grid = 2048 (16 batch x 64 segs x 2 strips), block = 256.
// Loads per thread: 10 warm-up + 8 steady = 18 (4B ab + 2B xy each).
// ---------------------------------------------------------------------------
__global__ void __launch_bounds__(256) k_pass2(float* __restrict__ out) {
    int blk = blockIdx.x;
    int xs  = blk & (XSPL - 1);  blk >>= 1;
    int seg = blk & (NSEG - 1);
    int b   = blk >> 6;
    int y0  = seg * SEG;
    int tid = threadIdx.x;
    int x   = (xs << 8) + tid;          // pixel column [0,512)

    const unsigned int* __restrict__ pab = g_ab + (size_t)b * HW + x;
    const __half*       __restrict__ pxy = g_xy + (size_t)b * HW + x;

    float axx = 0.f, ayy = 0.f, axy = 0.f;

    const __half hzero = __float2half(0.0f);

    // register ring: raw values of rows y0-5+i for i = 0..SEG-1
    unsigned int rva[SEG];
    __half       rxy[SEG];

    // warm-up: rows y0-5 .. y0+4, fully unrolled; save first SEG rows
#pragma unroll
    for (int j = 0; j < 2 * KRAD; j++) {
        int y = y0 - KRAD + j;
        unsigned int va = 0u;
        __half hb = hzero;
        if (y >= 0) {                       // y0+4 <= 508 < H always
            int r = y * W;
            va = __ldg(pab + r);
            hb = __ldg(pxy + r);
        }
        if (j < SEG) { rva[j] = va; rxy[j] = hb; }
        float2 f = __half22float2(*(const __half2*)&va);
        axx += f.x; ayy += f.y; axy += __half2float(hb);
    }

    float csum = 0.f;
#pragma unroll
    for (int i = 0; i < SEG; i++) {
        int ya = y0 + KRAD + i;
        unsigned int va = 0u;
        __half hb = hzero;
        if (ya < H) {
            int r = ya * W;
            va = __ldg(pab + r);
            hb = __ldg(pxy + r);
        }
        float2 f = __half22float2(*(const __half2*)&va);
        axx += f.x; ayy += f.y; axy += __half2float(hb);
        // cos = axy / (sqrt(axx)*sqrt(ayy) + 1e-6)  ~=  axy * rsqrt(axx*ayy)
        csum += axy * rsqrtf(axx * ayy);
        // subtract row y0-5+i from the register ring
        f = __half22float2(*(const __half2*)&rva[i]);
        axx -= f.x; ayy -= f.y; axy -= __half2float(rxy[i]);
    }

    // block reduce csum (8 warps)
    __shared__ float sred[8];
    int lane = tid & 31, wid = tid >> 5;
#pragma unroll
    for (int s = 16; s > 0; s >>= 1)
        csum += __shfl_xor_sync(0xffffffffu, csum, s);
    if (lane == 0) sred[wid] = csum;
    __syncthreads();
    if (tid == 0) {
        float t = sred[0] + sred[1] + sred[2] + sred[3]
                + sred[4] + sred[5] + sred[6] + sred[7];
        atomicAdd(&g_cos_sum, t);
    }

    // last-block fused finalize
    __shared__ unsigned int amLast;
    if (tid == 0) {
        __threadfence();
        amLast = (atomicAdd(&g_count, 1u) == (unsigned)(P2_BLOCKS - 1));
    }
    __syncthreads();
    if (amLast && tid < 32) {
        float v = 0.f;
        if (tid < BATCH)
            v = logf(g_mse[tid] * (1.0f / (float)(CH * HW)) + EPS_PSNR);
#pragma unroll
        for (int s = 16; s > 0; s >>= 1)
            v += __shfl_xor_sync(0xffffffffu, v, s);
        if (tid == 0) {
            const float scale = 10.0f / logf(10.0f);
            float psnr_loss = scale * (v * (1.0f / (float)BATCH));
            float lcs_loss  = 1.0f - g_cos_sum * (1.0f / (float)(BATCH * HW));
            out[0] = psnr_loss + lcs_loss;
            g_cos_sum = 0.0f;
            g_count = 0u;
        }
        if (tid < BATCH) g_mse[tid] = 0.0f;
    }
}

// ---------------------------------------------------------------------------
extern "C" void kernel_launch(void* const* d_in, const int* in_sizes, int n_in,
                              void* d_out, int out_size) {
    const float* pred = (const float*)d_in[0];
    const float* tgt  = (const float*)d_in[1];
    float* out = (float*)d_out;

    k_pass1<<<BATCH * H, 128>>>(pred, tgt);
    k_pass2<<<P2_BLOCKS, 256>>>(out);
}